// round 3
// baseline (speedup 1.0000x reference)
#include <cuda_runtime.h>
#include <cstdint>
#include <cstddef>

#define BB 256
#define TT 600
#define HID 512
#define NVOCAB 83

// d_out layout (floats): [0,21248) output probs ; [21248,152320) new_h ; [152320,305920) attn
#define OFF_NEWH 21248
#define OFF_ATTN 152320

// ---------------- scratch (no allocation allowed) ----------------
__device__ float g_ha[BB * HID];
__device__ float g_scores[BB * TT];
__device__ float g_ctx[BB * HID];
__device__ float g_indec[BB * 300];
__device__ float g_gi[BB * 1536];
__device__ float g_gh[BB * 1536];
__device__ float g_logits[BB * NVOCAB];

// ---------------- helpers ----------------
__device__ __forceinline__ uint32_t f2tf32(float x) {
    uint32_t r;
    asm("cvt.rna.tf32.f32 %0, %1;" : "=r"(r) : "f"(x));
    return r;
}

__device__ __forceinline__ void mma_tf32(float* c, const uint32_t* a, const uint32_t* b) {
    asm volatile(
        "mma.sync.aligned.m16n8k8.row.col.f32.tf32.tf32.f32 "
        "{%0,%1,%2,%3}, {%4,%5,%6,%7}, {%8,%9}, {%0,%1,%2,%3};\n"
        : "+f"(c[0]), "+f"(c[1]), "+f"(c[2]), "+f"(c[3])
        : "r"(a[0]), "r"(a[1]), "r"(a[2]), "r"(a[3]), "r"(b[0]), "r"(b[1]));
}

// ---------------- big fused scores kernel ----------------
// scores[b][t] = b_v + sum_n w_v[n] * tanh( (enc[t,b,:] @ W_ep)[n] + b_ep[n] + ha[b][n] )
// GEMM view: C[M=153600, N=512] = A[M,512] * W[512,512]; M row m = t*256 + b.
// Block: 64 rows, A panel (64x512) tf32-resident in smem; N in 4 chunks of 128;
// W double-buffered in 32-k slabs staged via registers.
#define ASTRIDE 516
#define WSTRIDE 136
#define WBUFSZ  (32 * WSTRIDE)
#define SMEM_SCORES (64 * ASTRIDE * 4 + 2 * WBUFSZ * 4 + 512 * 4 + 512 * 4 + 256 * 4)

__global__ void __launch_bounds__(256, 1)
scores_kernel(const float* __restrict__ enc, const float* __restrict__ Wep,
              const float* __restrict__ bep, const float* __restrict__ ha,
              const float* __restrict__ wv, const float* __restrict__ bv,
              float* __restrict__ scores) {
    extern __shared__ unsigned char smem_raw[];
    uint32_t* A_sm  = reinterpret_cast<uint32_t*>(smem_raw);        // 64*516
    uint32_t* W_sm  = A_sm + 64 * ASTRIDE;                          // 2*32*136
    float*    wv_sm = reinterpret_cast<float*>(W_sm + 2 * WBUFSZ);  // 512
    float*    bep_sm = wv_sm + 512;                                 // 512
    float*    stage = bep_sm + 512;                                 // 4*64

    const int tid = threadIdx.x;
    const int lane = tid & 31;
    const int w = tid >> 5;
    const int wm = w >> 2;        // 0..1  (M)
    const int wn = w & 3;         // 0..3  (N)
    const int g = lane >> 2;      // groupID
    const int t4 = lane & 3;      // threadID in group
    const int m0 = blockIdx.x * 64;

    for (int i = tid; i < 512; i += 256) { wv_sm[i] = wv[i]; bep_sm[i] = bep[i]; }

    // Load A panel (64 rows x 512 K), convert to tf32
#pragma unroll
    for (int i = 0; i < 32; i++) {
        int f4 = tid + i * 256;        // 0..8191
        int r = f4 >> 7;               // /128 float4 per row
        int c4 = f4 & 127;
        float4 v = *reinterpret_cast<const float4*>(enc + (size_t)(m0 + r) * 512 + (c4 << 2));
        uint32_t* d = A_sm + r * ASTRIDE + (c4 << 2);
        d[0] = f2tf32(v.x); d[1] = f2tf32(v.y); d[2] = f2tf32(v.z); d[3] = f2tf32(v.w);
    }
    __syncthreads();

    float spart[4] = {0.f, 0.f, 0.f, 0.f};
    float4 wreg[4];

    for (int nc = 0; nc < 4; nc++) {
        const int n0 = nc * 128;

        // register-staged W tile loaders
        auto loadWg = [&](int k0) {
#pragma unroll
            for (int i = 0; i < 4; i++) {
                int f4 = tid + i * 256;  // 0..1023
                int kr = f4 >> 5;        // /32
                int c4 = f4 & 31;
                wreg[i] = *reinterpret_cast<const float4*>(
                    Wep + (size_t)(k0 + kr) * 512 + n0 + (c4 << 2));
            }
        };
        auto storeW = [&](int buf) {
#pragma unroll
            for (int i = 0; i < 4; i++) {
                int f4 = tid + i * 256;
                int kr = f4 >> 5;
                int c4 = f4 & 31;
                uint32_t* d = W_sm + buf * WBUFSZ + kr * WSTRIDE + (c4 << 2);
                d[0] = f2tf32(wreg[i].x); d[1] = f2tf32(wreg[i].y);
                d[2] = f2tf32(wreg[i].z); d[3] = f2tf32(wreg[i].w);
            }
        };

        float acc[2][4][4];
#pragma unroll
        for (int mt = 0; mt < 2; mt++)
#pragma unroll
            for (int nt = 0; nt < 4; nt++)
#pragma unroll
                for (int q = 0; q < 4; q++) acc[mt][nt][q] = 0.f;

        loadWg(0);
        storeW(0);
        __syncthreads();

        for (int kb = 0; kb < 16; kb++) {
            if (kb < 15) loadWg((kb + 1) * 32);
            const uint32_t* Wb = W_sm + (kb & 1) * WBUFSZ;
#pragma unroll
            for (int ks = 0; ks < 4; ks++) {
                const int kA = kb * 32 + ks * 8 + t4;
                uint32_t afr[2][4];
#pragma unroll
                for (int mt = 0; mt < 2; mt++) {
                    const uint32_t* ap = A_sm + (wm * 32 + mt * 16 + g) * ASTRIDE + kA;
                    afr[mt][0] = ap[0];
                    afr[mt][1] = ap[8 * ASTRIDE];
                    afr[mt][2] = ap[4];
                    afr[mt][3] = ap[8 * ASTRIDE + 4];
                }
                uint32_t bfr[4][2];
#pragma unroll
                for (int nt = 0; nt < 4; nt++) {
                    const uint32_t* bp = Wb + (ks * 8 + t4) * WSTRIDE + wn * 32 + nt * 8 + g;
                    bfr[nt][0] = bp[0];
                    bfr[nt][1] = bp[4 * WSTRIDE];
                }
#pragma unroll
                for (int mt = 0; mt < 2; mt++)
#pragma unroll
                    for (int nt = 0; nt < 4; nt++)
                        mma_tf32(acc[mt][nt], afr[mt], bfr[nt]);
            }
            if (kb < 15) storeW((kb + 1) & 1);
            __syncthreads();
        }

        // fused epilogue for this N chunk: tanh + weighted reduce
#pragma unroll
        for (int mt = 0; mt < 2; mt++) {
#pragma unroll
            for (int nt = 0; nt < 4; nt++) {
                const int col0 = n0 + wn * 32 + nt * 8 + 2 * t4;
#pragma unroll
                for (int q = 0; q < 4; q++) {
                    const int rowl = wm * 32 + mt * 16 + g + ((q >> 1) << 3);
                    const int col = col0 + (q & 1);
                    const int brow = (m0 + rowl) & 255;
                    float v = acc[mt][nt][q] + ha[brow * 512 + col] + bep_sm[col];
                    spart[mt * 2 + (q >> 1)] += wv_sm[col] * tanhf(v);
                }
            }
        }
    }

    // deterministic reduction: within lane-group, then across the 4 N-warps via smem
#pragma unroll
    for (int i = 0; i < 4; i++) {
        spart[i] += __shfl_xor_sync(0xffffffffu, spart[i], 1);
        spart[i] += __shfl_xor_sync(0xffffffffu, spart[i], 2);
    }
    if (t4 == 0) {
#pragma unroll
        for (int i = 0; i < 4; i++) {
            int rowl = wm * 32 + (i >> 1) * 16 + (i & 1) * 8 + g;
            stage[wn * 64 + rowl] = spart[i];
        }
    }
    __syncthreads();
    if (tid < 64) {
        float s = stage[tid] + stage[64 + tid] + stage[128 + tid] + stage[192 + tid] + bv[0];
        int m = m0 + tid;
        scores[(m & 255) * TT + (m >> 8)] = s;
    }
}

// ---------------- generic tiled fp32 SGEMM + bias: C = A[MxK] * B[KxN] + bias ----------------
// grid: (ceil(N/64), M/64), 256 threads. M must be a multiple of 64 (always 256 here).
__global__ void __launch_bounds__(256)
sgemm_bias(const float* __restrict__ A, const float* __restrict__ B,
           const float* __restrict__ bias, float* __restrict__ C,
           int N, int K, int ldc) {
    __shared__ float As[16][68];
    __shared__ float Bs[16][68];
    const int tid = threadIdx.x;
    const int tx = tid & 15, ty = tid >> 4;
    const int m0 = blockIdx.y * 64, n0 = blockIdx.x * 64;
    float acc[4][4] = {};

    for (int k0 = 0; k0 < K; k0 += 16) {
#pragma unroll
        for (int i = 0; i < 4; i++) {
            int idx = tid + i * 256;   // 0..1023
            int r = idx >> 4, kc = idx & 15;
            float v = 0.f;
            if (k0 + kc < K) v = A[(size_t)(m0 + r) * K + k0 + kc];
            As[kc][r] = v;
        }
#pragma unroll
        for (int i = 0; i < 4; i++) {
            int idx = tid + i * 256;
            int kr = idx >> 6, c = idx & 63;
            float v = 0.f;
            if (k0 + kr < K && n0 + c < N) v = B[(size_t)(k0 + kr) * N + n0 + c];
            Bs[kr][c] = v;
        }
        __syncthreads();
#pragma unroll
        for (int kc = 0; kc < 16; kc++) {
            float a[4], bb[4];
#pragma unroll
            for (int i = 0; i < 4; i++) a[i] = As[kc][ty * 4 + i];
#pragma unroll
            for (int j = 0; j < 4; j++) bb[j] = Bs[kc][tx * 4 + j];
#pragma unroll
            for (int i = 0; i < 4; i++)
#pragma unroll
                for (int j = 0; j < 4; j++) acc[i][j] += a[i] * bb[j];
        }
        __syncthreads();
    }
#pragma unroll
    for (int i = 0; i < 4; i++) {
#pragma unroll
        for (int j = 0; j < 4; j++) {
            int col = n0 + tx * 4 + j;
            if (col < N)
                C[(size_t)(m0 + ty * 4 + i) * ldc + col] = acc[i][j] + bias[col];
        }
    }
}

// ---------------- softmax over T=600 -> attn in d_out ----------------
__global__ void softmax_attn(const float* __restrict__ scores, float* __restrict__ attn) {
    __shared__ float red[256];
    const int b = blockIdx.x, tid = threadIdx.x;
    const float* s = scores + b * TT;
    float* o = attn + b * TT;

    float m = -1e30f;
    for (int t = tid; t < TT; t += 256) m = fmaxf(m, s[t]);
    red[tid] = m;
    __syncthreads();
    for (int st = 128; st > 0; st >>= 1) {
        if (tid < st) red[tid] = fmaxf(red[tid], red[tid + st]);
        __syncthreads();
    }
    m = red[0];
    __syncthreads();

    float sum = 0.f;
    for (int t = tid; t < TT; t += 256) {
        float e = expf(s[t] - m);
        o[t] = e;
        sum += e;
    }
    red[tid] = sum;
    __syncthreads();
    for (int st = 128; st > 0; st >>= 1) {
        if (tid < st) red[tid] += red[tid + st];
        __syncthreads();
    }
    float inv = 1.f / red[0];
    for (int t = tid; t < TT; t += 256) o[t] *= inv;
}

// ---------------- context[b][h] = sum_t attn[b][t] * enc[t][b][h] ----------------
__global__ void __launch_bounds__(128)
context_kernel(const float* __restrict__ enc, const float* __restrict__ attn,
               float* __restrict__ ctx) {
    __shared__ float a_sm[TT];
    const int b = blockIdx.y, hc = blockIdx.x;
    const int tid = threadIdx.x;
    for (int t = tid; t < TT; t += 128) a_sm[t] = attn[b * TT + t];
    __syncthreads();
    const int h = hc * 128 + tid;
    const float* base = enc + (size_t)b * 512 + h;   // enc[t*131072 + b*512 + h]
    float a0 = 0.f, a1 = 0.f, a2 = 0.f, a3 = 0.f;
    for (int t = 0; t < TT; t += 4) {
        a0 += a_sm[t + 0] * base[(size_t)(t + 0) * 131072];
        a1 += a_sm[t + 1] * base[(size_t)(t + 1) * 131072];
        a2 += a_sm[t + 2] * base[(size_t)(t + 2) * 131072];
        a3 += a_sm[t + 3] * base[(size_t)(t + 3) * 131072];
    }
    ctx[b * 512 + h] = (a0 + a1) + (a2 + a3);
}

// ---------------- argmax over vocab + embedding gather into in_dec[:, 0:50] ----------------
__global__ void argmax_embed(const float* __restrict__ in_char, const float* __restrict__ emb,
                             float* __restrict__ indec) {
    const int b = threadIdx.x;   // 256 threads, 1 block
    const float* row = in_char + b * NVOCAB;
    float m = row[0];
    int idx = 0;
    for (int v = 1; v < NVOCAB; v++) {
        float x = row[v];
        if (x > m) { m = x; idx = v; }   // strict '>' keeps first max (matches argmax)
    }
    const float* e = emb + idx * 50;
    float* o = indec + b * 300;
    for (int j = 0; j < 50; j++) o[j] = e[j];
}

// ---------------- GRU cell elementwise ----------------
__global__ void gru_kernel(const float* __restrict__ gi, const float* __restrict__ gh,
                           const float* __restrict__ h, float* __restrict__ newh) {
    const int idx = blockIdx.x * 256 + threadIdx.x;   // < 131072
    const int b = idx >> 9, n = idx & 511;
    const float* gib = gi + b * 1536;
    const float* ghb = gh + b * 1536;
    float ir = gib[n], iz = gib[512 + n], in_ = gib[1024 + n];
    float hr = ghb[n], hz = ghb[512 + n], hn = ghb[1024 + n];
    float r = 1.f / (1.f + expf(-(ir + hr)));
    float z = 1.f / (1.f + expf(-(iz + hz)));
    float nn = tanhf(in_ + r * hn);
    newh[idx] = (1.f - z) * nn + z * h[idx];
}

// ---------------- output softmax over vocab ----------------
__global__ void __launch_bounds__(128)
softmax_out(const float* __restrict__ logits, float* __restrict__ out) {
    __shared__ float red[128];
    const int b = blockIdx.x, tid = threadIdx.x;
    float v = (tid < NVOCAB) ? logits[b * NVOCAB + tid] : -1e30f;
    red[tid] = v;
    __syncthreads();
    for (int st = 64; st > 0; st >>= 1) {
        if (tid < st) red[tid] = fmaxf(red[tid], red[tid + st]);
        __syncthreads();
    }
    float m = red[0];
    __syncthreads();
    float e = (tid < NVOCAB) ? expf(v - m) : 0.f;
    red[tid] = e;
    __syncthreads();
    for (int st = 64; st > 0; st >>= 1) {
        if (tid < st) red[tid] += red[tid + st];
        __syncthreads();
    }
    if (tid < NVOCAB) out[b * NVOCAB + tid] = e / red[0];
}

// ---------------- launch ----------------
extern "C" void kernel_launch(void* const* d_in, const int* in_sizes, int n_in,
                              void* d_out, int out_size) {
    const float* in_char = (const float*)d_in[0];
    const float* hidden  = (const float*)d_in[1];   // (1,B,512) == (B,512)
    const float* enc     = (const float*)d_in[2];   // (T,B,512)
    const float* W_hp = (const float*)d_in[3];
    const float* b_hp = (const float*)d_in[4];
    const float* W_ep = (const float*)d_in[5];
    const float* b_ep = (const float*)d_in[6];
    const float* w_v  = (const float*)d_in[7];
    const float* b_v  = (const float*)d_in[8];
    const float* W_cs = (const float*)d_in[9];
    const float* b_cs = (const float*)d_in[10];
    const float* emb  = (const float*)d_in[11];
    const float* W_ih = (const float*)d_in[12];
    const float* b_ih = (const float*)d_in[13];
    const float* W_hh = (const float*)d_in[14];
    const float* b_hh = (const float*)d_in[15];
    const float* W_out = (const float*)d_in[16];
    const float* b_out = (const float*)d_in[17];

    float* out = (float*)d_out;
    float* out_prob = out;
    float* out_newh = out + OFF_NEWH;
    float* out_attn = out + OFF_ATTN;

    float *ha, *scores, *ctx, *indec, *gi, *gh, *logits;
    cudaGetSymbolAddress((void**)&ha, g_ha);
    cudaGetSymbolAddress((void**)&scores, g_scores);
    cudaGetSymbolAddress((void**)&ctx, g_ctx);
    cudaGetSymbolAddress((void**)&indec, g_indec);
    cudaGetSymbolAddress((void**)&gi, g_gi);
    cudaGetSymbolAddress((void**)&gh, g_gh);
    cudaGetSymbolAddress((void**)&logits, g_logits);

    cudaFuncSetAttribute(scores_kernel, cudaFuncAttributeMaxDynamicSharedMemorySize,
                         SMEM_SCORES);

    // 1) hidden_attn = hidden @ W_hp + b_hp  (256x512x512)
    sgemm_bias<<<dim3(8, 4), 256>>>(hidden, W_hp, b_hp, ha, 512, 512, 512);

    // 2) fused scores (big GEMM + tanh + w_v reduce)
    scores_kernel<<<2400, 256, SMEM_SCORES>>>(enc, W_ep, b_ep, ha, w_v, b_v, scores);

    // 3) attn = softmax(scores) -> d_out
    softmax_attn<<<256, 256>>>(scores, out_attn);

    // 4) context = einsum('bth,bt->bh')
    context_kernel<<<dim3(4, 256), 128>>>(enc, out_attn, ctx);

    // 5) argmax + embedding into in_dec[:, :50]
    argmax_embed<<<1, 256>>>(in_char, emb, indec);

    // 6) in_dec[:, 50:300] = context @ W_cs + b_cs  (256x250x512, ldc=300)
    sgemm_bias<<<dim3(4, 4), 256>>>(ctx, W_cs, b_cs, indec + 50, 250, 512, 300);

    // 7) gi = in_dec @ W_ih + b_ih  (256x1536x300)
    sgemm_bias<<<dim3(24, 4), 256>>>(indec, W_ih, b_ih, gi, 1536, 300, 1536);

    // 8) gh = h @ W_hh + b_hh  (256x1536x512)
    sgemm_bias<<<dim3(24, 4), 256>>>(hidden, W_hh, b_hh, gh, 1536, 512, 1536);

    // 9) GRU -> new_h in d_out
    gru_kernel<<<512, 256>>>(gi, gh, hidden, out_newh);

    // 10) logits = new_h @ W_out + b_out  (256x83x512)
    sgemm_bias<<<dim3(2, 4), 256>>>(out_newh, W_out, b_out, logits, NVOCAB, 512, NVOCAB);

    // 11) output = softmax(logits) -> d_out
    softmax_out<<<256, 128>>>(logits, out_prob);
}

// round 6
// speedup vs baseline: 1.5710x; 1.5710x over previous
#include <cuda_runtime.h>
#include <cuda_fp16.h>
#include <cstdint>
#include <cstddef>

#define BB 256
#define TT 600
#define HID 512
#define NVOCAB 83

// d_out layout (floats): [0,21248) output probs ; [21248,152320) new_h ; [152320,305920) attn
#define OFF_NEWH 21248
#define OFF_ATTN 152320

// ---------------- scratch (no allocation allowed) ----------------
__device__ float g_ha[BB * HID];
__device__ float g_scores[BB * TT];
__device__ float g_ctx[BB * HID];
__device__ float g_indec[BB * 300];
__device__ float g_gi[BB * 1536];
__device__ float g_gh[BB * 1536];
__device__ float g_logits[BB * NVOCAB];
__device__ __half g_Wt[HID * HID];   // W_ep transposed + fp16: Wt[n][k]

// ---------------- helpers ----------------
__device__ __forceinline__ float tanh_fast(float x) {
    // tanh(x) = 1 - 2/(exp2(2x*log2e)+1); ~1e-6 abs error
    float e, r;
    asm("ex2.approx.f32 %0, %1;" : "=f"(e) : "f"(x * 2.8853900817779268f));
    asm("rcp.approx.f32 %0, %1;" : "=f"(r) : "f"(e + 1.0f));
    return 1.0f - 2.0f * r;
}

__device__ __forceinline__ void mma_fp16(float* c, const uint32_t* a, const uint32_t* b) {
    asm volatile(
        "mma.sync.aligned.m16n8k16.row.col.f32.f16.f16.f32 "
        "{%0,%1,%2,%3}, {%4,%5,%6,%7}, {%8,%9}, {%0,%1,%2,%3};\n"
        : "+f"(c[0]), "+f"(c[1]), "+f"(c[2]), "+f"(c[3])
        : "r"(a[0]), "r"(a[1]), "r"(a[2]), "r"(a[3]), "r"(b[0]), "r"(b[1]));
}

// ---------------- fused scores kernel (fp16 mma.sync) ----------------
// C[M=153600, N=512] = enc[M,512] @ W_ep[512,512]  (W pre-transposed fp16: Wt[n][k])
// scores[b][t] = b_v + sum_n w_v[n] * tanh(C[m][n] + ha[b][n] + b_ep[n]),  m = t*256 + b
// Block: 64 rows; A panel (64x512 fp16) smem-resident; N in 4 chunks of 128;
// K double-buffered in 64-wide slabs.
#define A_STRIDE_P 260                      // uint32 pairs per A row (520 halfs)
#define W_STRIDE_P 36                       // uint32 pairs per W row (72 halfs)
#define A_BYTES (64 * 520 * 2)              // 66560
#define W_BUF_U32 (128 * W_STRIDE_P)        // 4608 u32 = 18432 B
#define DYN_SMEM_SCORES (A_BYTES + 2 * W_BUF_U32 * 4)   // 103424

__global__ void __launch_bounds__(256, 2)
scores_fp16(const float* __restrict__ enc, const __half* __restrict__ Wt,
            const float* __restrict__ bep, const float* __restrict__ ha,
            const float* __restrict__ wv, const float* __restrict__ bv,
            float* __restrict__ scores) {
    extern __shared__ unsigned char dsm[];
    uint32_t* A32 = reinterpret_cast<uint32_t*>(dsm);                 // half-pairs
    uint32_t* W32 = reinterpret_cast<uint32_t*>(dsm + A_BYTES);       // 2 buffers
    __shared__ float wv_sm[512];
    __shared__ float bep_sm[512];
    __shared__ float stage_sm[256];

    const int tid = threadIdx.x;
    const int lane = tid & 31;
    const int w = tid >> 5;
    const int wm = w >> 2;        // 0..1  (M)
    const int wn = w & 3;         // 0..3  (N)
    const int g = lane >> 2;      // groupID (8)
    const int t4 = lane & 3;      // threadID in group
    const int m0 = blockIdx.x * 64;

    for (int i = tid; i < 512; i += 256) { wv_sm[i] = wv[i]; bep_sm[i] = bep[i]; }

    // Load A panel (64 x 512), convert fp32 -> fp16 pairs
#pragma unroll
    for (int i = 0; i < 32; i++) {
        int idx = tid + i * 256;        // 0..8191 (128 float4 per row)
        int r = idx >> 7, c4 = idx & 127;
        float4 v = *reinterpret_cast<const float4*>(enc + (size_t)(m0 + r) * 512 + (c4 << 2));
        __half2 h0 = __floats2half2_rn(v.x, v.y);
        __half2 h1 = __floats2half2_rn(v.z, v.w);
        uint32_t* d = A32 + r * A_STRIDE_P + c4 * 2;
        d[0] = *reinterpret_cast<uint32_t*>(&h0);
        d[1] = *reinterpret_cast<uint32_t*>(&h1);
    }
    __syncthreads();

    float spart[4] = {0.f, 0.f, 0.f, 0.f};
    uint4 wreg[4];

    for (int nc = 0; nc < 4; nc++) {
        const int n0 = nc * 128;

        auto loadW = [&](int k0) {
#pragma unroll
            for (int i = 0; i < 4; i++) {
                int idx = tid + i * 256;      // 0..1023 = 128 rows x 8 groups of 8 halfs
                int n = idx >> 3, g8 = idx & 7;
                wreg[i] = *reinterpret_cast<const uint4*>(
                    Wt + (size_t)(n0 + n) * 512 + k0 + g8 * 8);
            }
        };
        auto storeW = [&](int buf) {
            unsigned char* Wb = reinterpret_cast<unsigned char*>(W32 + buf * W_BUF_U32);
#pragma unroll
            for (int i = 0; i < 4; i++) {
                int idx = tid + i * 256;
                int n = idx >> 3, g8 = idx & 7;
                *reinterpret_cast<uint4*>(Wb + n * 144 + g8 * 16) = wreg[i];
            }
        };

        float acc[2][4][4];
#pragma unroll
        for (int mt = 0; mt < 2; mt++)
#pragma unroll
            for (int nt = 0; nt < 4; nt++)
#pragma unroll
                for (int q = 0; q < 4; q++) acc[mt][nt][q] = 0.f;

        loadW(0);
        storeW(0);
        __syncthreads();

        for (int s = 0; s < 8; s++) {
            if (s < 7) loadW((s + 1) * 64);
            const uint32_t* Wb = W32 + (s & 1) * W_BUF_U32;
            const int pb = s * 32;            // pair base of this 64-k slab
#pragma unroll
            for (int ks = 0; ks < 4; ks++) {
                const int pk = pb + ks * 8 + t4;
                uint32_t afr[2][4];
#pragma unroll
                for (int mt = 0; mt < 2; mt++) {
                    const uint32_t* ap = A32 + (wm * 32 + mt * 16 + g) * A_STRIDE_P + pk;
                    afr[mt][0] = ap[0];
                    afr[mt][1] = ap[8 * A_STRIDE_P];
                    afr[mt][2] = ap[4];
                    afr[mt][3] = ap[8 * A_STRIDE_P + 4];
                }
                uint32_t bfr[4][2];
#pragma unroll
                for (int nt = 0; nt < 4; nt++) {
                    const uint32_t* bp = Wb + (wn * 32 + nt * 8 + g) * W_STRIDE_P + ks * 8 + t4;
                    bfr[nt][0] = bp[0];
                    bfr[nt][1] = bp[4];
                }
#pragma unroll
                for (int mt = 0; mt < 2; mt++)
#pragma unroll
                    for (int nt = 0; nt < 4; nt++)
                        mma_fp16(acc[mt][nt], afr[mt], bfr[nt]);
            }
            if (s < 7) storeW((s + 1) & 1);
            __syncthreads();
        }

        // fused epilogue for this N chunk: + ha + b_ep, tanh, * w_v, accumulate
#pragma unroll
        for (int mt = 0; mt < 2; mt++) {
#pragma unroll
            for (int nt = 0; nt < 4; nt++) {
                const int col0 = n0 + wn * 32 + nt * 8 + 2 * t4;
#pragma unroll
                for (int q = 0; q < 4; q++) {
                    const int rowl = wm * 32 + mt * 16 + g + ((q >> 1) << 3);
                    const int col = col0 + (q & 1);
                    const int brow = (m0 + rowl) & 255;
                    float v = acc[mt][nt][q] + ha[(size_t)brow * 512 + col] + bep_sm[col];
                    spart[mt * 2 + (q >> 1)] += wv_sm[col] * tanh_fast(v);
                }
            }
        }
    }

    // deterministic reduction: within lane-group (t4), then across the 4 N-warps
#pragma unroll
    for (int i = 0; i < 4; i++) {
        spart[i] += __shfl_xor_sync(0xffffffffu, spart[i], 1);
        spart[i] += __shfl_xor_sync(0xffffffffu, spart[i], 2);
    }
    if (t4 == 0) {
#pragma unroll
        for (int i = 0; i < 4; i++) {
            int rowl = wm * 32 + (i >> 1) * 16 + (i & 1) * 8 + g;
            stage_sm[wn * 64 + rowl] = spart[i];
        }
    }
    __syncthreads();
    if (tid < 64) {
        float s = stage_sm[tid] + stage_sm[64 + tid] + stage_sm[128 + tid] +
                  stage_sm[192 + tid] + bv[0];
        int m = m0 + tid;
        scores[(size_t)(m & 255) * TT + (m >> 8)] = s;
    }
}

// ---------------- W_ep transpose+convert: Wt[n][k] = fp16(W[k][n]) ----------------
__global__ void transpose_h(const float* __restrict__ src, __half* __restrict__ dst) {
    __shared__ float t[32][33];
    const int tx = threadIdx.x, ty = threadIdx.y;
    const int kx = blockIdx.y * 32;
    const int nx = blockIdx.x * 32;
#pragma unroll
    for (int i = ty; i < 32; i += 8)
        t[i][tx] = src[(size_t)(kx + i) * 512 + nx + tx];
    __syncthreads();
#pragma unroll
    for (int i = ty; i < 32; i += 8)
        dst[(size_t)(nx + i) * 512 + kx + tx] = __float2half_rn(t[tx][i]);
}

// ---------------- generic tiled fp32 SGEMM + bias ----------------
__global__ void __launch_bounds__(256)
sgemm_bias(const float* __restrict__ A, const float* __restrict__ B,
           const float* __restrict__ bias, float* __restrict__ C,
           int N, int K, int ldc) {
    __shared__ float As[16][68];
    __shared__ float Bs[16][68];
    const int tid = threadIdx.x;
    const int tx = tid & 15, ty = tid >> 4;
    const int m0 = blockIdx.y * 64, n0 = blockIdx.x * 64;
    float acc[4][4] = {};

    for (int k0 = 0; k0 < K; k0 += 16) {
#pragma unroll
        for (int i = 0; i < 4; i++) {
            int idx = tid + i * 256;
            int r = idx >> 4, kc = idx & 15;
            float v = 0.f;
            if (k0 + kc < K) v = A[(size_t)(m0 + r) * K + k0 + kc];
            As[kc][r] = v;
        }
#pragma unroll
        for (int i = 0; i < 4; i++) {
            int idx = tid + i * 256;
            int kr = idx >> 6, c = idx & 63;
            float v = 0.f;
            if (k0 + kr < K && n0 + c < N) v = B[(size_t)(k0 + kr) * N + n0 + c];
            Bs[kr][c] = v;
        }
        __syncthreads();
#pragma unroll
        for (int kc = 0; kc < 16; kc++) {
            float a[4], bb[4];
#pragma unroll
            for (int i = 0; i < 4; i++) a[i] = As[kc][ty * 4 + i];
#pragma unroll
            for (int j = 0; j < 4; j++) bb[j] = Bs[kc][tx * 4 + j];
#pragma unroll
            for (int i = 0; i < 4; i++)
#pragma unroll
                for (int j = 0; j < 4; j++) acc[i][j] += a[i] * bb[j];
        }
        __syncthreads();
    }
#pragma unroll
    for (int i = 0; i < 4; i++) {
#pragma unroll
        for (int j = 0; j < 4; j++) {
            int col = n0 + tx * 4 + j;
            if (col < N)
                C[(size_t)(m0 + ty * 4 + i) * ldc + col] = acc[i][j] + bias[col];
        }
    }
}

// ---------------- softmax over T=600 -> attn in d_out ----------------
__global__ void softmax_attn(const float* __restrict__ scores, float* __restrict__ attn) {
    __shared__ float red[256];
    const int b = blockIdx.x, tid = threadIdx.x;
    const float* s = scores + b * TT;
    float* o = attn + b * TT;

    float m = -1e30f;
    for (int t = tid; t < TT; t += 256) m = fmaxf(m, s[t]);
    red[tid] = m;
    __syncthreads();
    for (int st = 128; st > 0; st >>= 1) {
        if (tid < st) red[tid] = fmaxf(red[tid], red[tid + st]);
        __syncthreads();
    }
    m = red[0];
    __syncthreads();

    float sum = 0.f;
    for (int t = tid; t < TT; t += 256) {
        float e = expf(s[t] - m);
        o[t] = e;
        sum += e;
    }
    red[tid] = sum;
    __syncthreads();
    for (int st = 128; st > 0; st >>= 1) {
        if (tid < st) red[tid] += red[tid + st];
        __syncthreads();
    }
    float inv = 1.f / red[0];
    for (int t = tid; t < TT; t += 256) o[t] *= inv;
}

// ---------------- context[b][h] = sum_t attn[b][t] * enc[t][b][h] ----------------
__global__ void __launch_bounds__(128)
context_kernel(const float* __restrict__ enc, const float* __restrict__ attn,
               float* __restrict__ ctx) {
    __shared__ float a_sm[TT];
    const int b = blockIdx.y, hc = blockIdx.x;
    const int tid = threadIdx.x;
    for (int t = tid; t < TT; t += 128) a_sm[t] = attn[b * TT + t];
    __syncthreads();
    const int h = hc * 128 + tid;
    const float* base = enc + (size_t)b * 512 + h;
    float a0 = 0.f, a1 = 0.f, a2 = 0.f, a3 = 0.f;
    for (int t = 0; t < TT; t += 4) {
        a0 += a_sm[t + 0] * base[(size_t)(t + 0) * 131072];
        a1 += a_sm[t + 1] * base[(size_t)(t + 1) * 131072];
        a2 += a_sm[t + 2] * base[(size_t)(t + 2) * 131072];
        a3 += a_sm[t + 3] * base[(size_t)(t + 3) * 131072];
    }
    ctx[b * 512 + h] = (a0 + a1) + (a2 + a3);
}

// ---------------- argmax over vocab + embedding gather ----------------
__global__ void argmax_embed(const float* __restrict__ in_char, const float* __restrict__ emb,
                             float* __restrict__ indec) {
    const int b = threadIdx.x;
    const float* row = in_char + b * NVOCAB;
    float m = row[0];
    int idx = 0;
    for (int v = 1; v < NVOCAB; v++) {
        float x = row[v];
        if (x > m) { m = x; idx = v; }
    }
    const float* e = emb + idx * 50;
    float* o = indec + b * 300;
    for (int j = 0; j < 50; j++) o[j] = e[j];
}

// ---------------- GRU cell elementwise ----------------
__global__ void gru_kernel(const float* __restrict__ gi, const float* __restrict__ gh,
                           const float* __restrict__ h, float* __restrict__ newh) {
    const int idx = blockIdx.x * 256 + threadIdx.x;
    const int b = idx >> 9, n = idx & 511;
    const float* gib = gi + b * 1536;
    const float* ghb = gh + b * 1536;
    float ir = gib[n], iz = gib[512 + n], in_ = gib[1024 + n];
    float hr = ghb[n], hz = ghb[512 + n], hn = ghb[1024 + n];
    float r = 1.f / (1.f + expf(-(ir + hr)));
    float z = 1.f / (1.f + expf(-(iz + hz)));
    float nn = tanhf(in_ + r * hn);
    newh[idx] = (1.f - z) * nn + z * h[idx];
}

// ---------------- output softmax over vocab ----------------
__global__ void __launch_bounds__(128)
softmax_out(const float* __restrict__ logits, float* __restrict__ out) {
    __shared__ float red[128];
    const int b = blockIdx.x, tid = threadIdx.x;
    float v = (tid < NVOCAB) ? logits[b * NVOCAB + tid] : -1e30f;
    red[tid] = v;
    __syncthreads();
    for (int st = 64; st > 0; st >>= 1) {
        if (tid < st) red[tid] = fmaxf(red[tid], red[tid + st]);
        __syncthreads();
    }
    float m = red[0];
    __syncthreads();
    float e = (tid < NVOCAB) ? expf(v - m) : 0.f;
    red[tid] = e;
    __syncthreads();
    for (int st = 64; st > 0; st >>= 1) {
        if (tid < st) red[tid] += red[tid + st];
        __syncthreads();
    }
    if (tid < NVOCAB) out[b * NVOCAB + tid] = e / red[0];
}

// ---------------- launch ----------------
extern "C" void kernel_launch(void* const* d_in, const int* in_sizes, int n_in,
                              void* d_out, int out_size) {
    const float* in_char = (const float*)d_in[0];
    const float* hidden  = (const float*)d_in[1];
    const float* enc     = (const float*)d_in[2];
    const float* W_hp = (const float*)d_in[3];
    const float* b_hp = (const float*)d_in[4];
    const float* W_ep = (const float*)d_in[5];
    const float* b_ep = (const float*)d_in[6];
    const float* w_v  = (const float*)d_in[7];
    const float* b_v  = (const float*)d_in[8];
    const float* W_cs = (const float*)d_in[9];
    const float* b_cs = (const float*)d_in[10];
    const float* emb  = (const float*)d_in[11];
    const float* W_ih = (const float*)d_in[12];
    const float* b_ih = (const float*)d_in[13];
    const float* W_hh = (const float*)d_in[14];
    const float* b_hh = (const float*)d_in[15];
    const float* W_out = (const float*)d_in[16];
    const float* b_out = (const float*)d_in[17];

    float* out = (float*)d_out;
    float* out_prob = out;
    float* out_newh = out + OFF_NEWH;
    float* out_attn = out + OFF_ATTN;

    float *ha, *scores, *ctx, *indec, *gi, *gh, *logits;
    __half* Wt;
    cudaGetSymbolAddress((void**)&ha, g_ha);
    cudaGetSymbolAddress((void**)&scores, g_scores);
    cudaGetSymbolAddress((void**)&ctx, g_ctx);
    cudaGetSymbolAddress((void**)&indec, g_indec);
    cudaGetSymbolAddress((void**)&gi, g_gi);
    cudaGetSymbolAddress((void**)&gh, g_gh);
    cudaGetSymbolAddress((void**)&logits, g_logits);
    cudaGetSymbolAddress((void**)&Wt, g_Wt);

    cudaFuncSetAttribute(scores_fp16, cudaFuncAttributeMaxDynamicSharedMemorySize,
                         DYN_SMEM_SCORES);

    // 0) transpose + fp16-convert W_ep -> Wt[n][k]
    transpose_h<<<dim3(16, 16), dim3(32, 8)>>>(W_ep, Wt);

    // 1) hidden_attn = hidden @ W_hp + b_hp  (256x512x512)
    sgemm_bias<<<dim3(8, 4), 256>>>(hidden, W_hp, b_hp, ha, 512, 512, 512);

    // 2) fused scores: fp16 mma GEMM + tanh + w_v reduce
    scores_fp16<<<2400, 256, DYN_SMEM_SCORES>>>(enc, Wt, b_ep, ha, w_v, b_v, scores);

    // 3) attn = softmax(scores) -> d_out
    softmax_attn<<<256, 256>>>(scores, out_attn);

    // 4) context = einsum('bth,bt->bh')
    context_kernel<<<dim3(4, 256), 128>>>(enc, out_attn, ctx);

    // 5) argmax + embedding into in_dec[:, :50]
    argmax_embed<<<1, 256>>>(in_char, emb, indec);

    // 6) in_dec[:, 50:300] = context @ W_cs + b_cs
    sgemm_bias<<<dim3(4, 4), 256>>>(ctx, W_cs, b_cs, indec + 50, 250, 512, 300);

    // 7) gi = in_dec @ W_ih + b_ih
    sgemm_bias<<<dim3(24, 4), 256>>>(indec, W_ih, b_ih, gi, 1536, 300, 1536);

    // 8) gh = h @ W_hh + b_hh
    sgemm_bias<<<dim3(24, 4), 256>>>(hidden, W_hh, b_hh, gh, 1536, 512, 1536);

    // 9) GRU -> new_h in d_out
    gru_kernel<<<512, 256>>>(gi, gh, hidden, out_newh);

    // 10) logits = new_h @ W_out + b_out
    sgemm_bias<<<dim3(2, 4), 256>>>(out_newh, W_out, b_out, logits, NVOCAB, 512, NVOCAB);

    // 11) output = softmax(logits) -> d_out
    softmax_out<<<256, 128>>>(logits, out_prob);
}

// round 7
// speedup vs baseline: 1.7445x; 1.1104x over previous
#include <cuda_runtime.h>
#include <cuda_fp16.h>
#include <cstdint>
#include <cstddef>

#define BB 256
#define TT 600
#define HID 512
#define NVOCAB 83

// d_out layout (floats): [0,21248) output probs ; [21248,152320) new_h ; [152320,305920) attn
#define OFF_NEWH 21248
#define OFF_ATTN 152320

// ---------------- scratch (no allocation allowed) ----------------
__device__ float g_ha[BB * HID];
__device__ float g_scores[BB * TT];
__device__ float g_ctx[BB * HID];
__device__ float g_indec[BB * 300];
__device__ float g_gi[BB * 1536];
__device__ float g_gh[BB * 1536];
__device__ float g_logits[BB * NVOCAB];
__device__ __half g_Wt[HID * HID];   // W_ep transposed + fp16: Wt[n][k]

// ---------------- helpers ----------------
__device__ __forceinline__ float tanh_fast(float x) {
    float e, r;
    asm("ex2.approx.f32 %0, %1;" : "=f"(e) : "f"(x * 2.8853900817779268f));
    asm("rcp.approx.f32 %0, %1;" : "=f"(r) : "f"(e + 1.0f));
    return 1.0f - 2.0f * r;
}

__device__ __forceinline__ void mma_fp16(float* c, const uint32_t* a, const uint32_t* b) {
    asm volatile(
        "mma.sync.aligned.m16n8k16.row.col.f32.f16.f16.f32 "
        "{%0,%1,%2,%3}, {%4,%5,%6,%7}, {%8,%9}, {%0,%1,%2,%3};\n"
        : "+f"(c[0]), "+f"(c[1]), "+f"(c[2]), "+f"(c[3])
        : "r"(a[0]), "r"(a[1]), "r"(a[2]), "r"(a[3]), "r"(b[0]), "r"(b[1]));
}

#define CP_ASYNC16(dst, src) \
    asm volatile("cp.async.cg.shared.global [%0], [%1], 16;" :: "r"(dst), "l"(src))
#define CP_COMMIT() asm volatile("cp.async.commit_group;" ::: "memory")
#define CP_WAIT1()  asm volatile("cp.async.wait_group 1;" ::: "memory")
#define CP_WAIT0()  asm volatile("cp.async.wait_group 0;" ::: "memory")

__device__ __forceinline__ uint32_t smem_u32(const void* p) {
    uint32_t a;
    asm("{ .reg .u64 t; cvta.to.shared.u64 t, %1; cvt.u32.u64 %0, t; }" : "=r"(a) : "l"(p));
    return a;
}

// ---------------- fused scores kernel (fp16 mma.sync, 128-row tiles) ----------------
// C[M=153600, N=512] = enc[M,512] @ W_ep[512,512]  (W pre-transposed fp16: Wt[n][k])
// scores[b][t] = b_v + sum_n w_v[n] * tanh(C[m][n] + ha[b][n] + b_ep[n]),  m = t*256 + b
// Block: 128 rows, A fp16 smem-resident; N in 2 chunks of 256; warp tile 64x64;
// W streamed in 64-K slabs via cp.async double buffer.
#define A_STRIDE_P 260                              // u32 pairs per A row (520 halfs)
#define A_SM_BYTES (128 * A_STRIDE_P * 4)           // 133120
#define W_STRIDE_P 36                               // u32 pairs per W row (144 B)
#define W_SLAB_U32 (256 * W_STRIDE_P)               // 9216 u32 = 36864 B
#define DYN_SMEM_SCORES (A_SM_BYTES + 2 * W_SLAB_U32 * 4)   // 206848

__global__ void __launch_bounds__(256, 1)
scores_fp16(const float* __restrict__ enc, const __half* __restrict__ Wt,
            const float* __restrict__ bep, const float* __restrict__ ha,
            const float* __restrict__ wv, const float* __restrict__ bv,
            float* __restrict__ scores) {
    extern __shared__ unsigned char dsm[];
    uint32_t* A32 = reinterpret_cast<uint32_t*>(dsm);
    uint32_t* W32 = reinterpret_cast<uint32_t*>(dsm + A_SM_BYTES);
    __shared__ float wv_sm[512];
    __shared__ float bep_sm[512];
    __shared__ float stage_sm[512];

    const int tid = threadIdx.x;
    const int lane = tid & 31;
    const int w = tid >> 5;
    const int wm = w >> 2;        // 0..1  (M half: 64 rows)
    const int wn = w & 3;         // 0..3  (N quarter: 64 cols)
    const int g = lane >> 2;      // 0..7
    const int t4 = lane & 3;      // 0..3
    const int m0 = blockIdx.x * 128;

    const uint32_t wsm_base = smem_u32(W32);

    // issue W slab for this thread: nc chunk, slab s (64 K), buffer buf
    auto issueW = [&](int nc, int s, int buf) {
#pragma unroll
        for (int i = 0; i < 8; i++) {
            int idx = tid + i * 256;              // 0..2047
            int n = idx >> 3, c8 = idx & 7;       // 256 rows x 8 chunks of 16B
            uint32_t dst = wsm_base + (uint32_t)buf * (W_SLAB_U32 * 4) + n * 144 + c8 * 16;
            const __half* src = Wt + (size_t)(nc * 256 + n) * 512 + s * 64 + c8 * 8;
            CP_ASYNC16(dst, src);
        }
        CP_COMMIT();
    };

    // prefetch first two W slabs of chunk 0 (overlaps A load below)
    issueW(0, 0, 0);
    issueW(0, 1, 1);

    for (int i = tid; i < 512; i += 256) { wv_sm[i] = wv[i]; bep_sm[i] = bep[i]; }

    // Load A panel (128 x 512), convert fp32 -> fp16 pairs, smem-resident
#pragma unroll 8
    for (int i = 0; i < 64; i++) {
        int idx = tid + i * 256;                  // 0..16383 (128 float4 per row)
        int r = idx >> 7, c4 = idx & 127;
        float4 v = *reinterpret_cast<const float4*>(enc + (size_t)(m0 + r) * 512 + (c4 << 2));
        __half2 h0 = __floats2half2_rn(v.x, v.y);
        __half2 h1 = __floats2half2_rn(v.z, v.w);
        uint32_t* d = A32 + r * A_STRIDE_P + c4 * 2;
        d[0] = *reinterpret_cast<uint32_t*>(&h0);
        d[1] = *reinterpret_cast<uint32_t*>(&h1);
    }
    __syncthreads();

    float spart[8];
#pragma unroll
    for (int i = 0; i < 8; i++) spart[i] = 0.f;

    for (int nc = 0; nc < 2; nc++) {
        float acc[4][8][4];
#pragma unroll
        for (int mt = 0; mt < 4; mt++)
#pragma unroll
            for (int nt = 0; nt < 8; nt++)
#pragma unroll
                for (int q = 0; q < 4; q++) acc[mt][nt][q] = 0.f;

#pragma unroll 2
        for (int s = 0; s < 8; s++) {
            if (s < 7) { CP_WAIT1(); } else { CP_WAIT0(); }
            __syncthreads();
            const uint32_t* Wb = W32 + (s & 1) * W_SLAB_U32;
#pragma unroll
            for (int ks = 0; ks < 4; ks++) {
                const int pk = s * 32 + ks * 8 + t4;
                uint32_t afr[4][4];
#pragma unroll
                for (int mt = 0; mt < 4; mt++) {
                    const uint32_t* ap = A32 + (wm * 64 + mt * 16 + g) * A_STRIDE_P + pk;
                    afr[mt][0] = ap[0];
                    afr[mt][1] = ap[8 * A_STRIDE_P];
                    afr[mt][2] = ap[4];
                    afr[mt][3] = ap[8 * A_STRIDE_P + 4];
                }
                uint32_t bfr[8][2];
#pragma unroll
                for (int nt = 0; nt < 8; nt++) {
                    const uint32_t* bp = Wb + (wn * 64 + nt * 8 + g) * W_STRIDE_P + ks * 8 + t4;
                    bfr[nt][0] = bp[0];
                    bfr[nt][1] = bp[4];
                }
#pragma unroll
                for (int mt = 0; mt < 4; mt++)
#pragma unroll
                    for (int nt = 0; nt < 8; nt++)
                        mma_fp16(acc[mt][nt], afr[mt], bfr[nt]);
            }
            __syncthreads();                       // all reads done before refill
            if (s < 6) issueW(nc, s + 2, s & 1);
        }

        // prefetch chunk-1 W while we run the chunk-0 epilogue
        if (nc == 0) { issueW(1, 0, 0); issueW(1, 1, 1); }

        // fused epilogue: + ha + b_ep, tanh, * w_v, accumulate into spart
#pragma unroll
        for (int mt = 0; mt < 4; mt++) {
#pragma unroll
            for (int qr = 0; qr < 2; qr++) {
                const int rowl = wm * 64 + mt * 16 + qr * 8 + g;
                const int brow = (m0 + rowl) & 255;
                const float* harow = ha + (size_t)brow * 512;
                float acc_s = 0.f;
#pragma unroll
                for (int nt = 0; nt < 8; nt++) {
                    const int col0 = nc * 256 + wn * 64 + nt * 8 + 2 * t4;
                    float2 hv = *reinterpret_cast<const float2*>(harow + col0);
                    float v0 = acc[mt][nt][qr * 2 + 0] + hv.x + bep_sm[col0];
                    float v1 = acc[mt][nt][qr * 2 + 1] + hv.y + bep_sm[col0 + 1];
                    acc_s += wv_sm[col0] * tanh_fast(v0);
                    acc_s += wv_sm[col0 + 1] * tanh_fast(v1);
                }
                spart[mt * 2 + qr] += acc_s;
            }
        }
    }

    // deterministic reduction: quad (t4) via shfl, then across the 4 N-warps via smem
#pragma unroll
    for (int i = 0; i < 8; i++) {
        spart[i] += __shfl_xor_sync(0xffffffffu, spart[i], 1);
        spart[i] += __shfl_xor_sync(0xffffffffu, spart[i], 2);
    }
    __syncthreads();
    if (t4 == 0) {
#pragma unroll
        for (int i = 0; i < 8; i++) {
            int rowl = wm * 64 + (i >> 1) * 16 + (i & 1) * 8 + g;
            stage_sm[wn * 128 + rowl] = spart[i];
        }
    }
    __syncthreads();
    if (tid < 128) {
        float s = stage_sm[tid] + stage_sm[128 + tid] + stage_sm[256 + tid] +
                  stage_sm[384 + tid] + bv[0];
        int m = m0 + tid;
        scores[(size_t)(m & 255) * TT + (m >> 8)] = s;
    }
}

// ---------------- W_ep transpose+convert: Wt[n][k] = fp16(W[k][n]) ----------------
__global__ void transpose_h(const float* __restrict__ src, __half* __restrict__ dst) {
    __shared__ float t[32][33];
    const int tx = threadIdx.x, ty = threadIdx.y;
    const int kx = blockIdx.y * 32;
    const int nx = blockIdx.x * 32;
#pragma unroll
    for (int i = ty; i < 32; i += 8)
        t[i][tx] = src[(size_t)(kx + i) * 512 + nx + tx];
    __syncthreads();
#pragma unroll
    for (int i = ty; i < 32; i += 8)
        dst[(size_t)(nx + i) * 512 + kx + tx] = __float2half_rn(t[tx][i]);
}

// ---------------- generic tiled fp32 SGEMM + bias ----------------
__global__ void __launch_bounds__(256)
sgemm_bias(const float* __restrict__ A, const float* __restrict__ B,
           const float* __restrict__ bias, float* __restrict__ C,
           int N, int K, int ldc) {
    __shared__ float As[16][68];
    __shared__ float Bs[16][68];
    const int tid = threadIdx.x;
    const int tx = tid & 15, ty = tid >> 4;
    const int m0 = blockIdx.y * 64, n0 = blockIdx.x * 64;
    float acc[4][4] = {};

    for (int k0 = 0; k0 < K; k0 += 16) {
#pragma unroll
        for (int i = 0; i < 4; i++) {
            int idx = tid + i * 256;
            int r = idx >> 4, kc = idx & 15;
            float v = 0.f;
            if (k0 + kc < K) v = A[(size_t)(m0 + r) * K + k0 + kc];
            As[kc][r] = v;
        }
#pragma unroll
        for (int i = 0; i < 4; i++) {
            int idx = tid + i * 256;
            int kr = idx >> 6, c = idx & 63;
            float v = 0.f;
            if (k0 + kr < K && n0 + c < N) v = B[(size_t)(k0 + kr) * N + n0 + c];
            Bs[kr][c] = v;
        }
        __syncthreads();
#pragma unroll
        for (int kc = 0; kc < 16; kc++) {
            float a[4], bb[4];
#pragma unroll
            for (int i = 0; i < 4; i++) a[i] = As[kc][ty * 4 + i];
#pragma unroll
            for (int j = 0; j < 4; j++) bb[j] = Bs[kc][tx * 4 + j];
#pragma unroll
            for (int i = 0; i < 4; i++)
#pragma unroll
                for (int j = 0; j < 4; j++) acc[i][j] += a[i] * bb[j];
        }
        __syncthreads();
    }
#pragma unroll
    for (int i = 0; i < 4; i++) {
#pragma unroll
        for (int j = 0; j < 4; j++) {
            int col = n0 + tx * 4 + j;
            if (col < N)
                C[(size_t)(m0 + ty * 4 + i) * ldc + col] = acc[i][j] + bias[col];
        }
    }
}

// ---------------- softmax over T=600 -> attn in d_out ----------------
__global__ void softmax_attn(const float* __restrict__ scores, float* __restrict__ attn) {
    __shared__ float red[256];
    const int b = blockIdx.x, tid = threadIdx.x;
    const float* s = scores + b * TT;
    float* o = attn + b * TT;

    float m = -1e30f;
    for (int t = tid; t < TT; t += 256) m = fmaxf(m, s[t]);
    red[tid] = m;
    __syncthreads();
    for (int st = 128; st > 0; st >>= 1) {
        if (tid < st) red[tid] = fmaxf(red[tid], red[tid + st]);
        __syncthreads();
    }
    m = red[0];
    __syncthreads();

    float sum = 0.f;
    for (int t = tid; t < TT; t += 256) {
        float e = expf(s[t] - m);
        o[t] = e;
        sum += e;
    }
    red[tid] = sum;
    __syncthreads();
    for (int st = 128; st > 0; st >>= 1) {
        if (tid < st) red[tid] += red[tid + st];
        __syncthreads();
    }
    float inv = 1.f / red[0];
    for (int t = tid; t < TT; t += 256) o[t] *= inv;
}

// ---------------- context[b][h] = sum_t attn[b][t] * enc[t][b][h] ----------------
__global__ void __launch_bounds__(128)
context_kernel(const float* __restrict__ enc, const float* __restrict__ attn,
               float* __restrict__ ctx) {
    __shared__ float a_sm[TT];
    const int b = blockIdx.y, hc = blockIdx.x;
    const int tid = threadIdx.x;
    for (int t = tid; t < TT; t += 128) a_sm[t] = attn[b * TT + t];
    __syncthreads();
    const int h = hc * 128 + tid;
    const float* base = enc + (size_t)b * 512 + h;
    float a0 = 0.f, a1 = 0.f, a2 = 0.f, a3 = 0.f;
    for (int t = 0; t < TT; t += 4) {
        a0 += a_sm[t + 0] * base[(size_t)(t + 0) * 131072];
        a1 += a_sm[t + 1] * base[(size_t)(t + 1) * 131072];
        a2 += a_sm[t + 2] * base[(size_t)(t + 2) * 131072];
        a3 += a_sm[t + 3] * base[(size_t)(t + 3) * 131072];
    }
    ctx[b * 512 + h] = (a0 + a1) + (a2 + a3);
}

// ---------------- argmax over vocab + embedding gather ----------------
__global__ void argmax_embed(const float* __restrict__ in_char, const float* __restrict__ emb,
                             float* __restrict__ indec) {
    const int b = threadIdx.x;
    const float* row = in_char + b * NVOCAB;
    float m = row[0];
    int idx = 0;
    for (int v = 1; v < NVOCAB; v++) {
        float x = row[v];
        if (x > m) { m = x; idx = v; }
    }
    const float* e = emb + idx * 50;
    float* o = indec + b * 300;
    for (int j = 0; j < 50; j++) o[j] = e[j];
}

// ---------------- GRU cell elementwise ----------------
__global__ void gru_kernel(const float* __restrict__ gi, const float* __restrict__ gh,
                           const float* __restrict__ h, float* __restrict__ newh) {
    const int idx = blockIdx.x * 256 + threadIdx.x;
    const int b = idx >> 9, n = idx & 511;
    const float* gib = gi + b * 1536;
    const float* ghb = gh + b * 1536;
    float ir = gib[n], iz = gib[512 + n], in_ = gib[1024 + n];
    float hr = ghb[n], hz = ghb[512 + n], hn = ghb[1024 + n];
    float r = 1.f / (1.f + expf(-(ir + hr)));
    float z = 1.f / (1.f + expf(-(iz + hz)));
    float nn = tanhf(in_ + r * hn);
    newh[idx] = (1.f - z) * nn + z * h[idx];
}

// ---------------- output softmax over vocab ----------------
__global__ void __launch_bounds__(128)
softmax_out(const float* __restrict__ logits, float* __restrict__ out) {
    __shared__ float red[128];
    const int b = blockIdx.x, tid = threadIdx.x;
    float v = (tid < NVOCAB) ? logits[b * NVOCAB + tid] : -1e30f;
    red[tid] = v;
    __syncthreads();
    for (int st = 64; st > 0; st >>= 1) {
        if (tid < st) red[tid] = fmaxf(red[tid], red[tid + st]);
        __syncthreads();
    }
    float m = red[0];
    __syncthreads();
    float e = (tid < NVOCAB) ? expf(v - m) : 0.f;
    red[tid] = e;
    __syncthreads();
    for (int st = 64; st > 0; st >>= 1) {
        if (tid < st) red[tid] += red[tid + st];
        __syncthreads();
    }
    if (tid < NVOCAB) out[b * NVOCAB + tid] = e / red[0];
}

// ---------------- launch ----------------
extern "C" void kernel_launch(void* const* d_in, const int* in_sizes, int n_in,
                              void* d_out, int out_size) {
    const float* in_char = (const float*)d_in[0];
    const float* hidden  = (const float*)d_in[1];
    const float* enc     = (const float*)d_in[2];
    const float* W_hp = (const float*)d_in[3];
    const float* b_hp = (const float*)d_in[4];
    const float* W_ep = (const float*)d_in[5];
    const float* b_ep = (const float*)d_in[6];
    const float* w_v  = (const float*)d_in[7];
    const float* b_v  = (const float*)d_in[8];
    const float* W_cs = (const float*)d_in[9];
    const float* b_cs = (const float*)d_in[10];
    const float* emb  = (const float*)d_in[11];
    const float* W_ih = (const float*)d_in[12];
    const float* b_ih = (const float*)d_in[13];
    const float* W_hh = (const float*)d_in[14];
    const float* b_hh = (const float*)d_in[15];
    const float* W_out = (const float*)d_in[16];
    const float* b_out = (const float*)d_in[17];

    float* out = (float*)d_out;
    float* out_prob = out;
    float* out_newh = out + OFF_NEWH;
    float* out_attn = out + OFF_ATTN;

    float *ha, *scores, *ctx, *indec, *gi, *gh, *logits;
    __half* Wt;
    cudaGetSymbolAddress((void**)&ha, g_ha);
    cudaGetSymbolAddress((void**)&scores, g_scores);
    cudaGetSymbolAddress((void**)&ctx, g_ctx);
    cudaGetSymbolAddress((void**)&indec, g_indec);
    cudaGetSymbolAddress((void**)&gi, g_gi);
    cudaGetSymbolAddress((void**)&gh, g_gh);
    cudaGetSymbolAddress((void**)&logits, g_logits);
    cudaGetSymbolAddress((void**)&Wt, g_Wt);

    cudaFuncSetAttribute(scores_fp16, cudaFuncAttributeMaxDynamicSharedMemorySize,
                         DYN_SMEM_SCORES);

    // 0) transpose + fp16-convert W_ep -> Wt[n][k]
    transpose_h<<<dim3(16, 16), dim3(32, 8)>>>(W_ep, Wt);

    // 1) hidden_attn = hidden @ W_hp + b_hp  (256x512x512)
    sgemm_bias<<<dim3(8, 4), 256>>>(hidden, W_hp, b_hp, ha, 512, 512, 512);

    // 2) fused scores: fp16 mma GEMM + tanh + w_v reduce
    scores_fp16<<<1200, 256, DYN_SMEM_SCORES>>>(enc, Wt, b_ep, ha, w_v, b_v, scores);

    // 3) attn = softmax(scores) -> d_out
    softmax_attn<<<256, 256>>>(scores, out_attn);

    // 4) context = einsum('bth,bt->bh')
    context_kernel<<<dim3(4, 256), 128>>>(enc, out_attn, ctx);

    // 5) argmax + embedding into in_dec[:, :50]
    argmax_embed<<<1, 256>>>(in_char, emb, indec);

    // 6) in_dec[:, 50:300] = context @ W_cs + b_cs
    sgemm_bias<<<dim3(4, 4), 256>>>(ctx, W_cs, b_cs, indec + 50, 250, 512, 300);

    // 7) gi = in_dec @ W_ih + b_ih
    sgemm_bias<<<dim3(24, 4), 256>>>(indec, W_ih, b_ih, gi, 1536, 300, 1536);

    // 8) gh = h @ W_hh + b_hh
    sgemm_bias<<<dim3(24, 4), 256>>>(hidden, W_hh, b_hh, gh, 1536, 512, 1536);

    // 9) GRU -> new_h in d_out
    gru_kernel<<<512, 256>>>(gi, gh, hidden, out_newh);

    // 10) logits = new_h @ W_out + b_out
    sgemm_bias<<<dim3(2, 4), 256>>>(out_newh, W_out, b_out, logits, NVOCAB, 512, NVOCAB);

    // 11) output = softmax(logits) -> d_out
    softmax_out<<<256, 128>>>(logits, out_prob);
}

// round 8
// speedup vs baseline: 1.9145x; 1.0974x over previous
#include <cuda_runtime.h>
#include <cuda_fp16.h>
#include <cstdint>
#include <cstddef>

#define BB 256
#define TT 600
#define HID 512
#define NVOCAB 83

// d_out layout (floats): [0,21248) output probs ; [21248,152320) new_h ; [152320,305920) attn
#define OFF_NEWH 21248
#define OFF_ATTN 152320

// ---------------- scratch (no allocation allowed) ----------------
__device__ float g_ha[BB * HID];
__device__ float g_scores[BB * TT];
__device__ float g_ctx[BB * HID];
__device__ float g_indec[BB * 300];
__device__ float g_gi[BB * 1536];
__device__ float g_gh[BB * 1536];
__device__ float g_logits[BB * NVOCAB];
__device__ __half g_Wt[HID * HID];   // W_ep transposed + fp16: Wt[n][k]

// ---------------- helpers ----------------
__device__ __forceinline__ float tanh_fast(float x) {
    float e, r;
    asm("ex2.approx.f32 %0, %1;" : "=f"(e) : "f"(x * 2.8853900817779268f));
    asm("rcp.approx.f32 %0, %1;" : "=f"(r) : "f"(e + 1.0f));
    return 1.0f - 2.0f * r;
}

__device__ __forceinline__ void mma_fp16(float* c, const uint32_t* a, const uint32_t* b) {
    asm volatile(
        "mma.sync.aligned.m16n8k16.row.col.f32.f16.f16.f32 "
        "{%0,%1,%2,%3}, {%4,%5,%6,%7}, {%8,%9}, {%0,%1,%2,%3};\n"
        : "+f"(c[0]), "+f"(c[1]), "+f"(c[2]), "+f"(c[3])
        : "r"(a[0]), "r"(a[1]), "r"(a[2]), "r"(a[3]), "r"(b[0]), "r"(b[1]));
}

__device__ __forceinline__ void ldsm_x4(uint32_t& r0, uint32_t& r1, uint32_t& r2,
                                        uint32_t& r3, uint32_t addr) {
    asm volatile("ldmatrix.sync.aligned.m8n8.x4.shared.b16 {%0,%1,%2,%3}, [%4];"
                 : "=r"(r0), "=r"(r1), "=r"(r2), "=r"(r3) : "r"(addr));
}

#define CP_ASYNC16(dst, src) \
    asm volatile("cp.async.cg.shared.global [%0], [%1], 16;" :: "r"(dst), "l"(src))
#define CP_COMMIT() asm volatile("cp.async.commit_group;" ::: "memory")
#define CP_WAIT1()  asm volatile("cp.async.wait_group 1;" ::: "memory")
#define CP_WAIT0()  asm volatile("cp.async.wait_group 0;" ::: "memory")

__device__ __forceinline__ uint32_t smem_u32(const void* p) {
    uint32_t a;
    asm("{ .reg .u64 t; cvta.to.shared.u64 t, %1; cvt.u32.u64 %0, t; }" : "=r"(a) : "l"(p));
    return a;
}

// ---------------- fused scores kernel (fp16 mma.sync + ldmatrix) ----------------
// C[M=153600, N=512] = enc[M,512] @ W_ep[512,512]  (W pre-transposed fp16: Wt[n][k])
// scores[b][t] = b_v + sum_n w_v[n] * tanh(C[m][n] + ha[b][n] + b_ep[n]),  m = t*256 + b
// Block: 128 rows, A fp16 smem-resident; N in 2 chunks of 256; warp tile 64x64;
// W streamed in 64-K slabs via cp.async double buffer; fragments via LDSM.
#define A_STRIDE_P 260                              // u32 pairs per A row (520 halfs, 1040 B)
#define A_SM_BYTES (128 * A_STRIDE_P * 4)           // 133120
#define W_STRIDE_P 36                               // u32 pairs per W row (144 B)
#define W_SLAB_U32 (256 * W_STRIDE_P)               // 9216 u32 = 36864 B
#define DYN_SMEM_SCORES (A_SM_BYTES + 2 * W_SLAB_U32 * 4)   // 206848

__global__ void __launch_bounds__(256, 1)
scores_fp16(const float* __restrict__ enc, const __half* __restrict__ Wt,
            const float* __restrict__ bep, const float* __restrict__ ha,
            const float* __restrict__ wv, const float* __restrict__ bv,
            float* __restrict__ scores) {
    extern __shared__ unsigned char dsm[];
    uint32_t* A32 = reinterpret_cast<uint32_t*>(dsm);
    uint32_t* W32 = reinterpret_cast<uint32_t*>(dsm + A_SM_BYTES);
    __shared__ float wv_sm[512];
    __shared__ float bep_sm[512];
    __shared__ float stage_sm[512];

    const int tid = threadIdx.x;
    const int lane = tid & 31;
    const int w = tid >> 5;
    const int wm = w >> 2;        // 0..1  (M half: 64 rows)
    const int wn = w & 3;         // 0..3  (N quarter: 64 cols)
    const int g = lane >> 2;      // 0..7
    const int t4 = lane & 3;      // 0..3
    const int m0 = blockIdx.x * 128;

    const uint32_t wsm_base = smem_u32(W32);
    const uint32_t asm_base = smem_u32(A32);

    // issue W slab: nc chunk, slab s (64 K), buffer buf
    auto issueW = [&](int nc, int s, int buf) {
#pragma unroll
        for (int i = 0; i < 8; i++) {
            int idx = tid + i * 256;              // 0..2047
            int n = idx >> 3, c8 = idx & 7;       // 256 rows x 8 chunks of 16B
            uint32_t dst = wsm_base + (uint32_t)buf * (W_SLAB_U32 * 4) + n * 144 + c8 * 16;
            const __half* src = Wt + (size_t)(nc * 256 + n) * 512 + s * 64 + c8 * 8;
            CP_ASYNC16(dst, src);
        }
        CP_COMMIT();
    };

    // prefetch first two W slabs of chunk 0 (overlaps A load below)
    issueW(0, 0, 0);
    issueW(0, 1, 1);

    for (int i = tid; i < 512; i += 256) { wv_sm[i] = wv[i]; bep_sm[i] = bep[i]; }

    // Load A panel (128 x 512), convert fp32 -> fp16 pairs, smem-resident
#pragma unroll 8
    for (int i = 0; i < 64; i++) {
        int idx = tid + i * 256;                  // 0..16383 (128 float4 per row)
        int r = idx >> 7, c4 = idx & 127;
        float4 v = *reinterpret_cast<const float4*>(enc + (size_t)(m0 + r) * 512 + (c4 << 2));
        __half2 h0 = __floats2half2_rn(v.x, v.y);
        __half2 h1 = __floats2half2_rn(v.z, v.w);
        uint32_t* d = A32 + r * A_STRIDE_P + c4 * 2;
        d[0] = *reinterpret_cast<uint32_t*>(&h0);
        d[1] = *reinterpret_cast<uint32_t*>(&h1);
    }
    __syncthreads();

    // ---- per-thread LDSM base addresses ----
    // A (row-major 16x16 frags): lanes 0-15 -> rows, bit4 -> +16B in k
    uint32_t a_addr[4];
    {
        int ar = wm * 64 + (lane & 15);
        int ak = (lane >> 4) * 16;
#pragma unroll
        for (int mt = 0; mt < 4; mt++)
            a_addr[mt] = asm_base + (uint32_t)((ar + mt * 16) * 1040 + ak);
    }
    // B ([n][k] rows, non-trans): lane&7 + bit4*8 -> n row, bit3 -> +16B in k
    uint32_t b_addr[2][4];
    {
        int br = wn * 64 + (lane & 7) + ((lane >> 4) & 1) * 8;
        int bk = ((lane >> 3) & 1) * 16;
#pragma unroll
        for (int buf = 0; buf < 2; buf++)
#pragma unroll
            for (int ntp = 0; ntp < 4; ntp++)
                b_addr[buf][ntp] = wsm_base + (uint32_t)buf * (W_SLAB_U32 * 4) +
                                   (uint32_t)((br + ntp * 16) * 144 + bk);
    }

    float spart[8];
#pragma unroll
    for (int i = 0; i < 8; i++) spart[i] = 0.f;

    for (int nc = 0; nc < 2; nc++) {
        float acc[4][8][4];
#pragma unroll
        for (int mt = 0; mt < 4; mt++)
#pragma unroll
            for (int nt = 0; nt < 8; nt++)
#pragma unroll
                for (int q = 0; q < 4; q++) acc[mt][nt][q] = 0.f;

        for (int s = 0; s < 8; s++) {
            if (s < 7) { CP_WAIT1(); } else { CP_WAIT0(); }
            __syncthreads();
            const int buf = s & 1;
            const uint32_t koff = (uint32_t)(s * 128);
#pragma unroll
            for (int ks = 0; ks < 4; ks++) {
                const uint32_t kb = koff + ks * 32;
                uint32_t afr[4][4];
#pragma unroll
                for (int mt = 0; mt < 4; mt++)
                    ldsm_x4(afr[mt][0], afr[mt][1], afr[mt][2], afr[mt][3],
                            a_addr[mt] + kb);
#pragma unroll
                for (int ntp = 0; ntp < 4; ntp++) {
                    uint32_t b0, b1, b2, b3;
                    ldsm_x4(b0, b1, b2, b3, b_addr[buf][ntp] + (uint32_t)(ks * 32));
                    uint32_t be[2] = { b0, b1 };
                    uint32_t bo[2] = { b2, b3 };
#pragma unroll
                    for (int mt = 0; mt < 4; mt++) {
                        mma_fp16(acc[mt][ntp * 2 + 0], afr[mt], be);
                        mma_fp16(acc[mt][ntp * 2 + 1], afr[mt], bo);
                    }
                }
            }
            __syncthreads();                       // all reads done before refill
            if (s < 6) issueW(nc, s + 2, s & 1);
        }

        // prefetch chunk-1 W while we run the chunk-0 epilogue
        if (nc == 0) { issueW(1, 0, 0); issueW(1, 1, 1); }

        // fused epilogue: + ha + b_ep, tanh, * w_v, accumulate into spart
#pragma unroll
        for (int mt = 0; mt < 4; mt++) {
#pragma unroll
            for (int qr = 0; qr < 2; qr++) {
                const int rowl = wm * 64 + mt * 16 + qr * 8 + g;
                const int brow = (m0 + rowl) & 255;
                const float* harow = ha + (size_t)brow * 512;
                float acc_s = 0.f;
#pragma unroll
                for (int nt = 0; nt < 8; nt++) {
                    const int col0 = nc * 256 + wn * 64 + nt * 8 + 2 * t4;
                    float2 hv = *reinterpret_cast<const float2*>(harow + col0);
                    float v0 = acc[mt][nt][qr * 2 + 0] + hv.x + bep_sm[col0];
                    float v1 = acc[mt][nt][qr * 2 + 1] + hv.y + bep_sm[col0 + 1];
                    acc_s += wv_sm[col0] * tanh_fast(v0);
                    acc_s += wv_sm[col0 + 1] * tanh_fast(v1);
                }
                spart[mt * 2 + qr] += acc_s;
            }
        }
    }

    // deterministic reduction: quad (t4) via shfl, then across the 4 N-warps via smem
#pragma unroll
    for (int i = 0; i < 8; i++) {
        spart[i] += __shfl_xor_sync(0xffffffffu, spart[i], 1);
        spart[i] += __shfl_xor_sync(0xffffffffu, spart[i], 2);
    }
    __syncthreads();
    if (t4 == 0) {
#pragma unroll
        for (int i = 0; i < 8; i++) {
            int rowl = wm * 64 + (i >> 1) * 16 + (i & 1) * 8 + g;
            stage_sm[wn * 128 + rowl] = spart[i];
        }
    }
    __syncthreads();
    if (tid < 128) {
        float s = stage_sm[tid] + stage_sm[128 + tid] + stage_sm[256 + tid] +
                  stage_sm[384 + tid] + bv[0];
        int m = m0 + tid;
        scores[(size_t)(m & 255) * TT + (m >> 8)] = s;
    }
}

// ---------------- W_ep transpose+convert: Wt[n][k] = fp16(W[k][n]) ----------------
__global__ void transpose_h(const float* __restrict__ src, __half* __restrict__ dst) {
    __shared__ float t[32][33];
    const int tx = threadIdx.x, ty = threadIdx.y;
    const int kx = blockIdx.y * 32;
    const int nx = blockIdx.x * 32;
#pragma unroll
    for (int i = ty; i < 32; i += 8)
        t[i][tx] = src[(size_t)(kx + i) * 512 + nx + tx];
    __syncthreads();
#pragma unroll
    for (int i = ty; i < 32; i += 8)
        dst[(size_t)(nx + i) * 512 + kx + tx] = __float2half_rn(t[tx][i]);
}

// ---------------- generic tiled fp32 SGEMM + bias ----------------
__global__ void __launch_bounds__(256)
sgemm_bias(const float* __restrict__ A, const float* __restrict__ B,
           const float* __restrict__ bias, float* __restrict__ C,
           int N, int K, int ldc) {
    __shared__ float As[16][68];
    __shared__ float Bs[16][68];
    const int tid = threadIdx.x;
    const int tx = tid & 15, ty = tid >> 4;
    const int m0 = blockIdx.y * 64, n0 = blockIdx.x * 64;
    float acc[4][4] = {};

    for (int k0 = 0; k0 < K; k0 += 16) {
#pragma unroll
        for (int i = 0; i < 4; i++) {
            int idx = tid + i * 256;
            int r = idx >> 4, kc = idx & 15;
            float v = 0.f;
            if (k0 + kc < K) v = A[(size_t)(m0 + r) * K + k0 + kc];
            As[kc][r] = v;
        }
#pragma unroll
        for (int i = 0; i < 4; i++) {
            int idx = tid + i * 256;
            int kr = idx >> 6, c = idx & 63;
            float v = 0.f;
            if (k0 + kr < K && n0 + c < N) v = B[(size_t)(k0 + kr) * N + n0 + c];
            Bs[kr][c] = v;
        }
        __syncthreads();
#pragma unroll
        for (int kc = 0; kc < 16; kc++) {
            float a[4], bb[4];
#pragma unroll
            for (int i = 0; i < 4; i++) a[i] = As[kc][ty * 4 + i];
#pragma unroll
            for (int j = 0; j < 4; j++) bb[j] = Bs[kc][tx * 4 + j];
#pragma unroll
            for (int i = 0; i < 4; i++)
#pragma unroll
                for (int j = 0; j < 4; j++) acc[i][j] += a[i] * bb[j];
        }
        __syncthreads();
    }
#pragma unroll
    for (int i = 0; i < 4; i++) {
#pragma unroll
        for (int j = 0; j < 4; j++) {
            int col = n0 + tx * 4 + j;
            if (col < N)
                C[(size_t)(m0 + ty * 4 + i) * ldc + col] = acc[i][j] + bias[col];
        }
    }
}

// ---------------- softmax over T=600 -> attn in d_out ----------------
__global__ void softmax_attn(const float* __restrict__ scores, float* __restrict__ attn) {
    __shared__ float red[256];
    const int b = blockIdx.x, tid = threadIdx.x;
    const float* s = scores + b * TT;
    float* o = attn + b * TT;

    float m = -1e30f;
    for (int t = tid; t < TT; t += 256) m = fmaxf(m, s[t]);
    red[tid] = m;
    __syncthreads();
    for (int st = 128; st > 0; st >>= 1) {
        if (tid < st) red[tid] = fmaxf(red[tid], red[tid + st]);
        __syncthreads();
    }
    m = red[0];
    __syncthreads();

    float sum = 0.f;
    for (int t = tid; t < TT; t += 256) {
        float e = expf(s[t] - m);
        o[t] = e;
        sum += e;
    }
    red[tid] = sum;
    __syncthreads();
    for (int st = 128; st > 0; st >>= 1) {
        if (tid < st) red[tid] += red[tid + st];
        __syncthreads();
    }
    float inv = 1.f / red[0];
    for (int t = tid; t < TT; t += 256) o[t] *= inv;
}

// ---------------- context[b][h] = sum_t attn[b][t] * enc[t][b][h] ----------------
__global__ void __launch_bounds__(128)
context_kernel(const float* __restrict__ enc, const float* __restrict__ attn,
               float* __restrict__ ctx) {
    __shared__ float a_sm[TT];
    const int b = blockIdx.y, hc = blockIdx.x;
    const int tid = threadIdx.x;
    for (int t = tid; t < TT; t += 128) a_sm[t] = attn[b * TT + t];
    __syncthreads();
    const int h = hc * 128 + tid;
    const float* base = enc + (size_t)b * 512 + h;
    float a0 = 0.f, a1 = 0.f, a2 = 0.f, a3 = 0.f;
    for (int t = 0; t < TT; t += 4) {
        a0 += a_sm[t + 0] * base[(size_t)(t + 0) * 131072];
        a1 += a_sm[t + 1] * base[(size_t)(t + 1) * 131072];
        a2 += a_sm[t + 2] * base[(size_t)(t + 2) * 131072];
        a3 += a_sm[t + 3] * base[(size_t)(t + 3) * 131072];
    }
    ctx[b * 512 + h] = (a0 + a1) + (a2 + a3);
}

// ---------------- argmax over vocab + embedding gather ----------------
__global__ void argmax_embed(const float* __restrict__ in_char, const float* __restrict__ emb,
                             float* __restrict__ indec) {
    const int b = threadIdx.x;
    const float* row = in_char + b * NVOCAB;
    float m = row[0];
    int idx = 0;
    for (int v = 1; v < NVOCAB; v++) {
        float x = row[v];
        if (x > m) { m = x; idx = v; }
    }
    const float* e = emb + idx * 50;
    float* o = indec + b * 300;
    for (int j = 0; j < 50; j++) o[j] = e[j];
}

// ---------------- GRU cell elementwise ----------------
__global__ void gru_kernel(const float* __restrict__ gi, const float* __restrict__ gh,
                           const float* __restrict__ h, float* __restrict__ newh) {
    const int idx = blockIdx.x * 256 + threadIdx.x;
    const int b = idx >> 9, n = idx & 511;
    const float* gib = gi + b * 1536;
    const float* ghb = gh + b * 1536;
    float ir = gib[n], iz = gib[512 + n], in_ = gib[1024 + n];
    float hr = ghb[n], hz = ghb[512 + n], hn = ghb[1024 + n];
    float r = 1.f / (1.f + expf(-(ir + hr)));
    float z = 1.f / (1.f + expf(-(iz + hz)));
    float nn = tanhf(in_ + r * hn);
    newh[idx] = (1.f - z) * nn + z * h[idx];
}

// ---------------- output softmax over vocab ----------------
__global__ void __launch_bounds__(128)
softmax_out(const float* __restrict__ logits, float* __restrict__ out) {
    __shared__ float red[128];
    const int b = blockIdx.x, tid = threadIdx.x;
    float v = (tid < NVOCAB) ? logits[b * NVOCAB + tid] : -1e30f;
    red[tid] = v;
    __syncthreads();
    for (int st = 64; st > 0; st >>= 1) {
        if (tid < st) red[tid] = fmaxf(red[tid], red[tid + st]);
        __syncthreads();
    }
    float m = red[0];
    __syncthreads();
    float e = (tid < NVOCAB) ? expf(v - m) : 0.f;
    red[tid] = e;
    __syncthreads();
    for (int st = 64; st > 0; st >>= 1) {
        if (tid < st) red[tid] += red[tid + st];
        __syncthreads();
    }
    if (tid < NVOCAB) out[b * NVOCAB + tid] = e / red[0];
}

// ---------------- launch ----------------
extern "C" void kernel_launch(void* const* d_in, const int* in_sizes, int n_in,
                              void* d_out, int out_size) {
    const float* in_char = (const float*)d_in[0];
    const float* hidden  = (const float*)d_in[1];
    const float* enc     = (const float*)d_in[2];
    const float* W_hp = (const float*)d_in[3];
    const float* b_hp = (const float*)d_in[4];
    const float* W_ep = (const float*)d_in[5];
    const float* b_ep = (const float*)d_in[6];
    const float* w_v  = (const float*)d_in[7];
    const float* b_v  = (const float*)d_in[8];
    const float* W_cs = (const float*)d_in[9];
    const float* b_cs = (const float*)d_in[10];
    const float* emb  = (const float*)d_in[11];
    const float* W_ih = (const float*)d_in[12];
    const float* b_ih = (const float*)d_in[13];
    const float* W_hh = (const float*)d_in[14];
    const float* b_hh = (const float*)d_in[15];
    const float* W_out = (const float*)d_in[16];
    const float* b_out = (const float*)d_in[17];

    float* out = (float*)d_out;
    float* out_prob = out;
    float* out_newh = out + OFF_NEWH;
    float* out_attn = out + OFF_ATTN;

    float *ha, *scores, *ctx, *indec, *gi, *gh, *logits;
    __half* Wt;
    cudaGetSymbolAddress((void**)&ha, g_ha);
    cudaGetSymbolAddress((void**)&scores, g_scores);
    cudaGetSymbolAddress((void**)&ctx, g_ctx);
    cudaGetSymbolAddress((void**)&indec, g_indec);
    cudaGetSymbolAddress((void**)&gi, g_gi);
    cudaGetSymbolAddress((void**)&gh, g_gh);
    cudaGetSymbolAddress((void**)&logits, g_logits);
    cudaGetSymbolAddress((void**)&Wt, g_Wt);

    cudaFuncSetAttribute(scores_fp16, cudaFuncAttributeMaxDynamicSharedMemorySize,
                         DYN_SMEM_SCORES);

    // 0) transpose + fp16-convert W_ep -> Wt[n][k]
    transpose_h<<<dim3(16, 16), dim3(32, 8)>>>(W_ep, Wt);

    // 1) hidden_attn = hidden @ W_hp + b_hp  (256x512x512)
    sgemm_bias<<<dim3(8, 4), 256>>>(hidden, W_hp, b_hp, ha, 512, 512, 512);

    // 2) fused scores: fp16 mma GEMM (ldmatrix) + tanh + w_v reduce
    scores_fp16<<<1200, 256, DYN_SMEM_SCORES>>>(enc, Wt, b_ep, ha, w_v, b_v, scores);

    // 3) attn = softmax(scores) -> d_out
    softmax_attn<<<256, 256>>>(scores, out_attn);

    // 4) context = einsum('bth,bt->bh')
    context_kernel<<<dim3(4, 256), 128>>>(enc, out_attn, ctx);

    // 5) argmax + embedding into in_dec[:, :50]
    argmax_embed<<<1, 256>>>(in_char, emb, indec);

    // 6) in_dec[:, 50:300] = context @ W_cs + b_cs
    sgemm_bias<<<dim3(4, 4), 256>>>(ctx, W_cs, b_cs, indec + 50, 250, 512, 300);

    // 7) gi = in_dec @ W_ih + b_ih
    sgemm_bias<<<dim3(24, 4), 256>>>(indec, W_ih, b_ih, gi, 1536, 300, 1536);

    // 8) gh = h @ W_hh + b_hh
    sgemm_bias<<<dim3(24, 4), 256>>>(hidden, W_hh, b_hh, gh, 1536, 512, 1536);

    // 9) GRU -> new_h in d_out
    gru_kernel<<<512, 256>>>(gi, gh, hidden, out_newh);

    // 10) logits = new_h @ W_out + b_out
    sgemm_bias<<<dim3(2, 4), 256>>>(out_newh, W_out, b_out, logits, NVOCAB, 512, NVOCAB);

    // 11) output = softmax(logits) -> d_out
    softmax_out<<<256, 128>>>(logits, out_prob);
}